// round 3
// baseline (speedup 1.0000x reference)
#include <cuda_runtime.h>

// Mann eddy-lifetime: tau = gamma * rsqrt(t2 * w^{1/3} * s(w)),
//   t2 = (L*|k|)^2, w = 1/(1+t2), s = 2F1(1/3,-3/2,4/3,w) (Pfaff series).
// Degree-12 truncation: tail <= ~1e-4 rel worst-case, 12x under 1e-3 gate.

constexpr int NDEG = 12;

struct PolyCoeffs { float c[NDEG + 1]; };

__host__ __device__ constexpr PolyCoeffs make_coeffs() {
    PolyCoeffs p{};
    double term = 1.0;
    p.c[0] = 1.0f;
    for (int n = 0; n < NDEG; ++n) {
        // a = 1/3, bp = c - b = -3/2, c = 4/3
        term *= ((1.0 / 3.0 + n) * (n - 1.5)) / ((4.0 / 3.0 + n) * (n + 1.0));
        p.c[n + 1] = (float)term;
    }
    return p;
}

__device__ __forceinline__ float frcp(float x) { float r; asm("rcp.approx.f32 %0, %1;"   : "=f"(r) : "f"(x)); return r; }
__device__ __forceinline__ float flg2(float x) { float r; asm("lg2.approx.f32 %0, %1;"   : "=f"(r) : "f"(x)); return r; }
__device__ __forceinline__ float fex2(float x) { float r; asm("ex2.approx.f32 %0, %1;"   : "=f"(r) : "f"(x)); return r; }
__device__ __forceinline__ float frsq(float x) { float r; asm("rsqrt.approx.f32 %0, %1;" : "=f"(r) : "f"(x)); return r; }

typedef unsigned long long u64;

__device__ __forceinline__ u64 pack2(float lo, float hi) {
    u64 r; asm("mov.b64 %0, {%1, %2};" : "=l"(r) : "f"(lo), "f"(hi)); return r;
}
__device__ __forceinline__ void unpack2(u64 v, float& lo, float& hi) {
    asm("mov.b64 {%0, %1}, %2;" : "=f"(lo), "=f"(hi) : "l"(v));
}
__device__ __forceinline__ u64 fma2(u64 a, u64 b, u64 c) {
    u64 d; asm("fma.rn.f32x2 %0, %1, %2, %3;" : "=l"(d) : "l"(a), "l"(b), "l"(c)); return d;
}
__device__ __forceinline__ u64 mul2(u64 a, u64 b) {
    u64 d; asm("mul.rn.f32x2 %0, %1, %2;" : "=l"(d) : "l"(a), "l"(b)); return d;
}

// 8 elements per thread: 6x LDG.128 in, 2x STG.128 out; packed f32x2 Horner.
__global__ void __launch_bounds__(256)
mann_kernel8(const float4* __restrict__ k4,
             const float* __restrict__ Lp,
             const float* __restrict__ gp,
             float4* __restrict__ out,
             int n8) {
    int i = blockIdx.x * blockDim.x + threadIdx.x;
    if (i >= n8) return;

    const float L  = __ldg(Lp);
    const float g  = __ldg(gp);
    const float L2 = L * L;

    const float4* base = k4 + 6 * i;
    float4 v0 = base[0], v1 = base[1], v2 = base[2];
    float4 v3 = base[3], v4 = base[4], v5 = base[5];

    float t[8];
    t[0] = L2 * fmaf(v0.x, v0.x, fmaf(v0.y, v0.y, v0.z * v0.z));
    t[1] = L2 * fmaf(v0.w, v0.w, fmaf(v1.x, v1.x, v1.y * v1.y));
    t[2] = L2 * fmaf(v1.z, v1.z, fmaf(v1.w, v1.w, v2.x * v2.x));
    t[3] = L2 * fmaf(v2.y, v2.y, fmaf(v2.z, v2.z, v2.w * v2.w));
    t[4] = L2 * fmaf(v3.x, v3.x, fmaf(v3.y, v3.y, v3.z * v3.z));
    t[5] = L2 * fmaf(v3.w, v3.w, fmaf(v4.x, v4.x, v4.y * v4.y));
    t[6] = L2 * fmaf(v4.z, v4.z, fmaf(v4.w, v4.w, v5.x * v5.x));
    t[7] = L2 * fmaf(v5.y, v5.y, fmaf(v5.z, v5.z, v5.w * v5.w));

    constexpr PolyCoeffs P = make_coeffs();
    u64 cp[NDEG + 1];
#pragma unroll
    for (int n = 0; n <= NDEG; ++n) cp[n] = pack2(P.c[n], P.c[n]);

    float r[8];
#pragma unroll
    for (int p = 0; p < 4; ++p) {
        float ta = t[2 * p], tb = t[2 * p + 1];
        float wa = frcp(1.0f + ta);
        float wb = frcp(1.0f + tb);

        u64 w2 = pack2(wa, wb);
        u64 s2 = cp[NDEG];
#pragma unroll
        for (int n = NDEG - 1; n >= 0; --n) s2 = fma2(s2, w2, cp[n]);

        float ca = fex2(0.33333334f * flg2(wa));   // wa^{1/3}
        float cb = fex2(0.33333334f * flg2(wb));   // wb^{1/3}

        u64 x2 = mul2(pack2(ta * ca, tb * cb), s2);
        float xa, xb;
        unpack2(x2, xa, xb);

        float ra = frsq(xa);
        float rb = frsq(xb);
        r[2 * p]     = (ta > 0.0f) ? g * ra : 0.0f;
        r[2 * p + 1] = (tb > 0.0f) ? g * rb : 0.0f;
    }

    out[2 * i]     = make_float4(r[0], r[1], r[2], r[3]);
    out[2 * i + 1] = make_float4(r[4], r[5], r[6], r[7]);
}

// Scalar tail for out_size not divisible by 8.
__device__ __forceinline__ float mann_tau_scalar(float t2) {
    constexpr PolyCoeffs P = make_coeffs();
    float w = frcp(1.0f + t2);
    float s = P.c[NDEG];
#pragma unroll
    for (int n = NDEG - 1; n >= 0; --n) s = fmaf(s, w, P.c[n]);
    float cw = fex2(0.33333334f * flg2(w));
    float r = frsq(t2 * cw * s);
    return (t2 > 0.0f) ? r : 0.0f;
}

__global__ void mann_kernel1(const float* __restrict__ k,
                             const float* __restrict__ Lp,
                             const float* __restrict__ gp,
                             float* __restrict__ out,
                             int start, int n) {
    int i = start + blockIdx.x * blockDim.x + threadIdx.x;
    if (i >= n) return;
    float L = __ldg(Lp);
    float g = __ldg(gp);
    float x = k[3 * i + 0], y = k[3 * i + 1], z = k[3 * i + 2];
    float t2 = (L * L) * fmaf(x, x, fmaf(y, y, z * z));
    out[i] = g * mann_tau_scalar(t2);
}

extern "C" void kernel_launch(void* const* d_in, const int* in_sizes, int n_in,
                              void* d_out, int out_size) {
    const float* k = (const float*)d_in[0];
    const float* L = (const float*)d_in[1];
    const float* g = (const float*)d_in[2];
    float* out = (float*)d_out;

    int n8 = out_size >> 3;
    if (n8 > 0) {
        int blocks = (n8 + 255) / 256;
        mann_kernel8<<<blocks, 256>>>((const float4*)k, L, g, (float4*)out, n8);
    }
    int done = n8 << 3;
    int rem = out_size - done;
    if (rem > 0) {
        mann_kernel1<<<(rem + 127) / 128, 128>>>(k, L, g, out, done, out_size);
    }
}

// round 4
// speedup vs baseline: 1.0013x; 1.0013x over previous
#include <cuda_runtime.h>

// Mann eddy-lifetime: tau = gamma * rsqrt(t2 * w^{1/3} * s(w)),
//   t2 = (L*|k|)^2, w = 1/(1+t2), s = 2F1(1/3,-3/2,4/3,w) (Pfaff series).
// Degree-12 truncation: tail ~1e-4 rel worst-case, well under 1e-3 gate.

constexpr int NDEG = 12;

struct PolyCoeffs { float c[NDEG + 1]; };

__host__ __device__ constexpr PolyCoeffs make_coeffs() {
    PolyCoeffs p{};
    double term = 1.0;
    p.c[0] = 1.0f;
    for (int n = 0; n < NDEG; ++n) {
        // a = 1/3, bp = c - b = -3/2, c = 4/3
        term *= ((1.0 / 3.0 + n) * (n - 1.5)) / ((4.0 / 3.0 + n) * (n + 1.0));
        p.c[n + 1] = (float)term;
    }
    return p;
}

__device__ __forceinline__ float frcp(float x) { float r; asm("rcp.approx.f32 %0, %1;"   : "=f"(r) : "f"(x)); return r; }
__device__ __forceinline__ float flg2(float x) { float r; asm("lg2.approx.f32 %0, %1;"   : "=f"(r) : "f"(x)); return r; }
__device__ __forceinline__ float fex2(float x) { float r; asm("ex2.approx.f32 %0, %1;"   : "=f"(r) : "f"(x)); return r; }
__device__ __forceinline__ float frsq(float x) { float r; asm("rsqrt.approx.f32 %0, %1;" : "=f"(r) : "f"(x)); return r; }

typedef unsigned long long u64;

__device__ __forceinline__ u64 pack2(float lo, float hi) {
    u64 r; asm("mov.b64 %0, {%1, %2};" : "=l"(r) : "f"(lo), "f"(hi)); return r;
}
__device__ __forceinline__ void unpack2(u64 v, float& lo, float& hi) {
    asm("mov.b64 {%0, %1}, %2;" : "=f"(lo), "=f"(hi) : "l"(v));
}
__device__ __forceinline__ u64 fma2(u64 a, u64 b, u64 c) {
    u64 d; asm("fma.rn.f32x2 %0, %1, %2, %3;" : "=l"(d) : "l"(a), "l"(b), "l"(c)); return d;
}
__device__ __forceinline__ u64 mul2(u64 a, u64 b) {
    u64 d; asm("mul.rn.f32x2 %0, %1, %2;" : "=l"(d) : "l"(a), "l"(b)); return d;
}

// Block = 256 threads, 1024 elements (768 float4 of k, 256 float4 of out).
// Global loads fully coalesced (3 stripes), smem transpose is bank-conflict-free
// (LDS.128 at 48B stride: words 12l..12l+3 cover all 32 banks once per phase).
__global__ void __launch_bounds__(256)
mann_smem(const float4* __restrict__ k4,
          const float* __restrict__ Lp,
          const float* __restrict__ gp,
          float4* __restrict__ out) {
    __shared__ float4 sf[768];

    const int blk = blockIdx.x;
    const int t   = threadIdx.x;

    const float4* base = k4 + (size_t)blk * 768;
    sf[t]       = base[t];
    sf[t + 256] = base[t + 256];
    sf[t + 512] = base[t + 512];

    const float L  = __ldg(Lp);
    const float g  = __ldg(gp);
    const float L2 = L * L;

    __syncthreads();

    float4 a = sf[3 * t + 0];
    float4 b = sf[3 * t + 1];
    float4 c = sf[3 * t + 2];

    float t0 = L2 * fmaf(a.x, a.x, fmaf(a.y, a.y, a.z * a.z));
    float t1 = L2 * fmaf(a.w, a.w, fmaf(b.x, b.x, b.y * b.y));
    float t2 = L2 * fmaf(b.z, b.z, fmaf(b.w, b.w, c.x * c.x));
    float t3 = L2 * fmaf(c.y, c.y, fmaf(c.z, c.z, c.w * c.w));

    constexpr PolyCoeffs P = make_coeffs();
    u64 cp[NDEG + 1];
#pragma unroll
    for (int n = 0; n <= NDEG; ++n) cp[n] = pack2(P.c[n], P.c[n]);

    float r[4];
    float tt[4] = {t0, t1, t2, t3};
#pragma unroll
    for (int p = 0; p < 2; ++p) {
        float ta = tt[2 * p], tb = tt[2 * p + 1];
        float wa = frcp(1.0f + ta);
        float wb = frcp(1.0f + tb);

        u64 w2 = pack2(wa, wb);
        u64 s2 = cp[NDEG];
#pragma unroll
        for (int n = NDEG - 1; n >= 0; --n) s2 = fma2(s2, w2, cp[n]);

        float ca = fex2(0.33333334f * flg2(wa));   // wa^{1/3}
        float cb = fex2(0.33333334f * flg2(wb));   // wb^{1/3}

        u64 x2 = mul2(pack2(ta * ca, tb * cb), s2);
        float xa, xb;
        unpack2(x2, xa, xb);

        r[2 * p]     = (ta > 0.0f) ? g * frsq(xa) : 0.0f;
        r[2 * p + 1] = (tb > 0.0f) ? g * frsq(xb) : 0.0f;
    }

    out[(size_t)blk * 256 + t] = make_float4(r[0], r[1], r[2], r[3]);
}

// Scalar tail for out_size not divisible by 1024.
__device__ __forceinline__ float mann_tau_scalar(float t2) {
    constexpr PolyCoeffs P = make_coeffs();
    float w = frcp(1.0f + t2);
    float s = P.c[NDEG];
#pragma unroll
    for (int n = NDEG - 1; n >= 0; --n) s = fmaf(s, w, P.c[n]);
    float cw = fex2(0.33333334f * flg2(w));
    float r = frsq(t2 * cw * s);
    return (t2 > 0.0f) ? r : 0.0f;
}

__global__ void mann_kernel1(const float* __restrict__ k,
                             const float* __restrict__ Lp,
                             const float* __restrict__ gp,
                             float* __restrict__ out,
                             int start, int n) {
    int i = start + blockIdx.x * blockDim.x + threadIdx.x;
    if (i >= n) return;
    float L = __ldg(Lp);
    float g = __ldg(gp);
    float x = k[3 * i + 0], y = k[3 * i + 1], z = k[3 * i + 2];
    float t2 = (L * L) * fmaf(x, x, fmaf(y, y, z * z));
    out[i] = g * mann_tau_scalar(t2);
}

extern "C" void kernel_launch(void* const* d_in, const int* in_sizes, int n_in,
                              void* d_out, int out_size) {
    const float* k = (const float*)d_in[0];
    const float* L = (const float*)d_in[1];
    const float* g = (const float*)d_in[2];
    float* out = (float*)d_out;

    int nfull = out_size >> 10;           // blocks of 1024 elements
    if (nfull > 0) {
        mann_smem<<<nfull, 256>>>((const float4*)k, L, g, (float4*)out);
    }
    int done = nfull << 10;
    int rem = out_size - done;
    if (rem > 0) {
        mann_kernel1<<<(rem + 127) / 128, 128>>>(k, L, g, out, done, out_size);
    }
}